// round 3
// baseline (speedup 1.0000x reference)
#include <cuda_runtime.h>
#include <cstdint>

#define BB   8
#define CC   256
#define CQ   32
#define NN   16384
#define TN   64
#define NTIL (NN / TN)      // 256
#define EPSV 1e-6f
#define XST  72             // stride mod 32 = 8 -> conflict-free frags
#define KST  72

// ---------------- scratch (device globals) ---------------------------------
__device__ __align__(16) uint32_t g_WtF[4 * 32 * 32 * 4];   // tf32 A-frags: [wo][kk][lane].xyzw ; wo 0-1 = Wq, 2-3 = Wk
__device__ float g_mpT[BB * CC * CQ];                       // (Kn @ x^T)^T : [b][c][m]
__device__ float g_S[BB * CQ];                              // sum_n Kn
__device__ float g_xsum[BB * CC];                           // sum_n x
__device__ __align__(16) uint32_t g_mfrag[BB * 16 * 4 * 32 * 4]; // matT tf32 A-frags [b][ct][kk][lane].xyzw
__device__ float g_vsum[BB * CC];                           // value_sum

__device__ __forceinline__ uint32_t f2tf(float f) {
    uint32_t r; asm("cvt.rna.tf32.f32 %0, %1;" : "=r"(r) : "f"(f)); return r;
}

__device__ __forceinline__ void mma_tf32(float& d0, float& d1, float& d2, float& d3,
                                         uint32_t a0, uint32_t a1, uint32_t a2, uint32_t a3,
                                         uint32_t b0, uint32_t b1) {
    asm volatile(
        "mma.sync.aligned.m16n8k8.row.col.f32.tf32.tf32.f32 "
        "{%0,%1,%2,%3},{%4,%5,%6,%7},{%8,%9},{%0,%1,%2,%3};"
        : "+f"(d0), "+f"(d1), "+f"(d2), "+f"(d3)
        : "r"(a0), "r"(a1), "r"(a2), "r"(a3), "r"(b0), "r"(b1));
}

// ---------------- kernel 0: zero accumulators + build tf32 W-fragments -----
__global__ void k_prep(const float* __restrict__ Wq, const float* __restrict__ Wk) {
    int idx = blockIdx.x * blockDim.x + threadIdx.x;      // 65536 threads
    if (idx < BB * CC * CQ) g_mpT[idx] = 0.f;
    if (idx < 16384) {
        int f    = idx & 3;
        int lane = (idx >> 2) & 31;
        int kk   = (idx >> 7) & 31;
        int wo   = idx >> 12;
        int gid = lane >> 2, tig = lane & 3;
        int o = (wo & 1) * 16 + gid + (f & 1) * 8;
        int c = kk * 8 + tig + (f >> 1) * 4;
        float v = (wo < 2) ? Wq[o * CC + c] : Wk[o * CC + c];
        g_WtF[idx] = f2tf(v);
    }
    if (idx < BB * CC) g_xsum[idx] = 0.f;
    if (idx < BB * CQ) g_S[idx] = 0.f;
}

// ---------------- kernel 1: K-only pass: Kn, S, xsum, mpT -------------------
__global__ void __launch_bounds__(256, 2)
k_pass1(const float* __restrict__ x, const float* __restrict__ bk) {
    extern __shared__ float sh[];
    float* xs  = sh;                        // [256][XST]  x tile (tf32 bits)
    float* qks = sh + CC * XST;             // [32][KST]   K rows -> Kn (tf32)
    float* rn  = qks + CQ * KST;            // [64]
    uint32_t* xsu  = (uint32_t*)xs;
    uint32_t* qksu = (uint32_t*)qks;

    const int b   = blockIdx.x >> 8;
    const int n0  = (blockIdx.x & 255) * TN;
    const int tid = threadIdx.x;
    const int w    = tid >> 5;
    const int lane = tid & 31;
    const int gid  = lane >> 2;
    const int tig  = lane & 3;
    const float* xb = x + (size_t)b * CC * NN;

    // stage x tile as tf32 (coalesced float4 loads)
    for (int idx = tid; idx < CC * 16; idx += 256) {
        int c = idx >> 4, q = idx & 15;
        float4 v = *(const float4*)(xb + (size_t)c * NN + n0 + 4 * q);
        uint4 t;
        t.x = f2tf(v.x); t.y = f2tf(v.y); t.z = f2tf(v.z); t.w = f2tf(v.w);
        *(uint4*)&xsu[c * XST + 4 * q] = t;
    }
    __syncthreads();

    // K[32o x 64j] = Wk @ x-tile ; warp: wo = w&1 (16 o), wj = w>>1 (16 j)
    {
        const int wo = w & 1;
        const int wj = w >> 1;
        float d0[2], d1[2], d2[2], d3[2];
        #pragma unroll
        for (int s = 0; s < 2; s++) { d0[s] = d1[s] = d2[s] = d3[s] = 0.f; }

        const uint4* WtF = (const uint4*)g_WtF + ((2 + wo) * 32) * 32 + lane;
        #pragma unroll 4
        for (int kk = 0; kk < 32; kk++) {
            uint4 a = WtF[kk * 32];
            const int c0 = kk * 8;
            #pragma unroll
            for (int s = 0; s < 2; s++) {
                int j = 16 * wj + 8 * s + gid;
                uint32_t b0 = xsu[(c0 + tig) * XST + j];
                uint32_t b1 = xsu[(c0 + 4 + tig) * XST + j];
                mma_tf32(d0[s], d1[s], d2[s], d3[s], a.x, a.y, a.z, a.w, b0, b1);
            }
        }
        const int o1 = 16 * wo + gid;
        const int o2 = o1 + 8;
        const float bi1 = __ldg(&bk[o1]);
        const float bi2 = __ldg(&bk[o2]);
        #pragma unroll
        for (int s = 0; s < 2; s++) {
            int j = 16 * wj + 8 * s + 2 * tig;
            qks[o1 * KST + j]     = d0[s] + bi1;
            qks[o1 * KST + j + 1] = d1[s] + bi1;
            qks[o2 * KST + j]     = d2[s] + bi2;
            qks[o2 * KST + j + 1] = d3[s] + bi2;
        }
    }
    __syncthreads();

    // rnorm per column
    if (tid < 64) {
        float s = 0.f;
        #pragma unroll
        for (int o = 0; o < 32; o++) {
            float v = qks[o * KST + tid];
            s += v * v;
        }
        rn[tid] = rsqrtf(s);
    }
    __syncthreads();

    // Kn tf32 in place
    for (int idx = tid; idx < CQ * TN; idx += 256) {
        int m = idx >> 6, j = idx & 63;
        float v = qks[m * KST + j] * rn[j];
        qksu[m * KST + j] = f2tf(v);
    }
    __syncthreads();

    // S and xsum partials
    if (tid < 32) {
        float s = 0.f;
        #pragma unroll
        for (int j = 0; j < TN; j++) s += qks[tid * KST + j];
        atomicAdd(&g_S[b * CQ + tid], s);
    }
    {
        float s = 0.f;
        #pragma unroll
        for (int j = 0; j < TN; j++) s += xs[tid * XST + j];
        atomicAdd(&g_xsum[b * CC + tid], s);
    }

    // mpT[256c x 32m] += x-tile @ Kn^T  (k = 64)
    {
        float e[2][4][4];
        #pragma unroll
        for (int ct = 0; ct < 2; ct++)
            #pragma unroll
            for (int mt = 0; mt < 4; mt++)
                #pragma unroll
                for (int q = 0; q < 4; q++) e[ct][mt][q] = 0.f;

        #pragma unroll
        for (int kk = 0; kk < 8; kk++) {
            const int j0 = kk * 8;
            uint32_t a[2][4];
            #pragma unroll
            for (int ct = 0; ct < 2; ct++) {
                int c0 = (2 * w + ct) * 16;
                a[ct][0] = xsu[(c0 + gid) * XST + j0 + tig];
                a[ct][1] = xsu[(c0 + 8 + gid) * XST + j0 + tig];
                a[ct][2] = xsu[(c0 + gid) * XST + j0 + 4 + tig];
                a[ct][3] = xsu[(c0 + 8 + gid) * XST + j0 + 4 + tig];
            }
            uint32_t bb0[4], bb1[4];
            #pragma unroll
            for (int mt = 0; mt < 4; mt++) {
                int m0 = mt * 8;
                bb0[mt] = qksu[(m0 + gid) * KST + j0 + tig];
                bb1[mt] = qksu[(m0 + gid) * KST + j0 + 4 + tig];
            }
            #pragma unroll
            for (int ct = 0; ct < 2; ct++)
                #pragma unroll
                for (int mt = 0; mt < 4; mt++)
                    mma_tf32(e[ct][mt][0], e[ct][mt][1], e[ct][mt][2], e[ct][mt][3],
                             a[ct][0], a[ct][1], a[ct][2], a[ct][3], bb0[mt], bb1[mt]);
        }
        float* mpb = &g_mpT[b * CC * CQ];
        #pragma unroll
        for (int ct = 0; ct < 2; ct++) {
            int c0 = (2 * w + ct) * 16;
            #pragma unroll
            for (int mt = 0; mt < 4; mt++) {
                int m0 = mt * 8 + 2 * tig;
                atomicAdd(&mpb[(c0 + gid) * CQ + m0],         e[ct][mt][0]);
                atomicAdd(&mpb[(c0 + gid) * CQ + m0 + 1],     e[ct][mt][1]);
                atomicAdd(&mpb[(c0 + 8 + gid) * CQ + m0],     e[ct][mt][2]);
                atomicAdd(&mpb[(c0 + 8 + gid) * CQ + m0 + 1], e[ct][mt][3]);
            }
        }
    }
}

// ---------------- kernel 2: matrix = mp @ Wv^T + bv (x) S ; vsum; fragments -
__global__ void __launch_bounds__(256)
k_mat(const float* __restrict__ Wv, const float* __restrict__ bv) {
    __shared__ float mpT[CC * CQ];   // [c][m]
    __shared__ float xs_s[CC];
    __shared__ float S_s[CQ];
    const int b = blockIdx.x, tid = threadIdx.x;

    for (int idx = tid; idx < CC * CQ; idx += 256)
        mpT[idx] = g_mpT[b * CC * CQ + idx];
    xs_s[tid] = g_xsum[b * CC + tid];
    if (tid < 32) S_s[tid] = g_S[b * CQ + tid];
    __syncthreads();

    const int cp = tid;                         // output channel c'
    float bvv = __ldg(&bv[cp]);
    float accm[32];
    #pragma unroll
    for (int m = 0; m < 32; m++) accm[m] = bvv * S_s[m];
    float vs = (float)NN * bvv;

    const float* wrow = Wv + cp * CC;
    for (int c = 0; c < CC; ++c) {
        float wv = __ldg(&wrow[c]);
        vs += wv * xs_s[c];
        const float4* mr = (const float4*)&mpT[c * CQ];
        #pragma unroll
        for (int q = 0; q < 8; q++) {
            float4 v = mr[q];
            accm[q * 4 + 0] += v.x * wv; accm[q * 4 + 1] += v.y * wv;
            accm[q * 4 + 2] += v.z * wv; accm[q * 4 + 3] += v.w * wv;
        }
    }
    g_vsum[b * CC + cp] = vs;

    // scatter matT row cp into tf32 A-fragment layout
    const int ct = cp >> 4, cl = cp & 15;
    const int gid = cl & 7, hi = cl >> 3;
    #pragma unroll
    for (int m = 0; m < 32; m++) {
        int kk = m >> 3, tig = m & 3, half = (m >> 2) & 1;
        int elem = hi + 2 * half;
        g_mfrag[((((b * 16 + ct) * 4 + kk) * 32) + gid * 4 + tig) * 4 + elem] = f2tf(accm[m]);
    }
}

// ---------------- kernel 3: pass 2: recompute Qn, TC epilogue ---------------
__global__ void __launch_bounds__(256, 2)
k_pass2(const float* __restrict__ x, const float* __restrict__ bq,
        const float* __restrict__ gamma, float* __restrict__ out) {
    extern __shared__ float sh[];
    float* xs   = sh;                       // [256][XST]  x tile fp32
    float* qn   = xs + CC * XST;            // [32][KST]   Q -> Qn (tf32)
    float* rn   = qn + CQ * KST;            // [64]
    float* gt   = rn + 64;                  // [64]
    float* vs_s = gt + 64;                  // [256]
    float* Se   = vs_s + CC;                // [32]
    uint32_t* qnu = (uint32_t*)qn;

    const int b   = blockIdx.x >> 8;
    const int n0  = (blockIdx.x & 255) * TN;
    const int tid = threadIdx.x;
    const int w    = tid >> 5;
    const int lane = tid & 31;
    const int gid  = lane >> 2;
    const int tig  = lane & 3;
    const float* xb = x + (size_t)b * CC * NN;

    // stage x tile fp32 + broadcast vs, S
    for (int idx = tid; idx < CC * 16; idx += 256) {
        int c = idx >> 4, q = idx & 15;
        *(float4*)&xs[c * XST + 4 * q] =
            *(const float4*)(xb + (size_t)c * NN + n0 + 4 * q);
    }
    vs_s[tid] = g_vsum[b * CC + tid];
    if (tid < 32) Se[tid] = g_S[b * CQ + tid] + EPSV;
    __syncthreads();

    // Q[32o x 64j] = Wq @ x-tile (cvt B on load)
    {
        const int wo = w & 1;
        const int wj = w >> 1;
        float d0[2], d1[2], d2[2], d3[2];
        #pragma unroll
        for (int s = 0; s < 2; s++) { d0[s] = d1[s] = d2[s] = d3[s] = 0.f; }

        const uint4* WtF = (const uint4*)g_WtF + (wo * 32) * 32 + lane;
        #pragma unroll 4
        for (int kk = 0; kk < 32; kk++) {
            uint4 a = WtF[kk * 32];
            const int c0 = kk * 8;
            #pragma unroll
            for (int s = 0; s < 2; s++) {
                int j = 16 * wj + 8 * s + gid;
                uint32_t b0 = f2tf(xs[(c0 + tig) * XST + j]);
                uint32_t b1 = f2tf(xs[(c0 + 4 + tig) * XST + j]);
                mma_tf32(d0[s], d1[s], d2[s], d3[s], a.x, a.y, a.z, a.w, b0, b1);
            }
        }
        const int o1 = 16 * wo + gid;
        const int o2 = o1 + 8;
        const float bi1 = __ldg(&bq[o1]);
        const float bi2 = __ldg(&bq[o2]);
        #pragma unroll
        for (int s = 0; s < 2; s++) {
            int j = 16 * wj + 8 * s + 2 * tig;
            qn[o1 * KST + j]     = d0[s] + bi1;
            qn[o1 * KST + j + 1] = d1[s] + bi1;
            qn[o2 * KST + j]     = d2[s] + bi2;
            qn[o2 * KST + j + 1] = d3[s] + bi2;
        }
    }
    __syncthreads();

    if (tid < 64) {
        float s = 0.f;
        #pragma unroll
        for (int o = 0; o < 32; o++) {
            float v = qn[o * KST + tid];
            s += v * v;
        }
        rn[tid] = rsqrtf(s);
    }
    __syncthreads();

    for (int idx = tid; idx < CQ * TN; idx += 256) {
        int m = idx >> 6, j = idx & 63;
        float v = qn[m * KST + j] * rn[j];
        qnu[m * KST + j] = f2tf(v);
    }
    __syncthreads();

    if (tid < 64) {
        float tl = 0.f;
        #pragma unroll
        for (int m = 0; m < 32; m++) tl += qn[m * KST + tid] * Se[m];
        gt[tid] = __ldg(&gamma[0]) / ((float)NN + tl);
    }
    __syncthreads();

    // D[c][j] = sum_m matT[c][m] * Qn[m][j] ; epilogue fused, direct store
    {
        uint4 A[2][4];
        #pragma unroll
        for (int ct = 0; ct < 2; ct++)
            #pragma unroll
            for (int kk = 0; kk < 4; kk++)
                A[ct][kk] = *((const uint4*)g_mfrag +
                              ((b * 16 + 2 * w + ct) * 4 + kk) * 32 + lane);

        float* ob = out + (size_t)b * CC * NN + n0;

        #pragma unroll 1
        for (int jt = 0; jt < 8; jt++) {
            uint32_t B0[4], B1[4];
            #pragma unroll
            for (int kk = 0; kk < 4; kk++) {
                B0[kk] = qnu[(kk * 8 + tig) * KST + jt * 8 + gid];
                B1[kk] = qnu[(kk * 8 + 4 + tig) * KST + jt * 8 + gid];
            }
            const int j = jt * 8 + 2 * tig;
            const float gt0 = gt[j], gt1 = gt[j + 1];
            #pragma unroll
            for (int ct = 0; ct < 2; ct++) {
                float e0 = 0.f, e1 = 0.f, e2 = 0.f, e3 = 0.f;
                #pragma unroll
                for (int kk = 0; kk < 4; kk++)
                    mma_tf32(e0, e1, e2, e3,
                             A[ct][kk].x, A[ct][kk].y, A[ct][kk].z, A[ct][kk].w,
                             B0[kk], B1[kk]);
                const int c1 = (2 * w + ct) * 16 + gid;
                const int c2 = c1 + 8;
                float2 o1v, o2v;
                o1v.x = xs[c1 * XST + j]     + gt0 * (vs_s[c1] + e0);
                o1v.y = xs[c1 * XST + j + 1] + gt1 * (vs_s[c1] + e1);
                o2v.x = xs[c2 * XST + j]     + gt0 * (vs_s[c2] + e2);
                o2v.y = xs[c2 * XST + j + 1] + gt1 * (vs_s[c2] + e3);
                *(float2*)(ob + (size_t)c1 * NN + j) = o1v;
                *(float2*)(ob + (size_t)c2 * NN + j) = o2v;
            }
        }
    }
}

// ---------------- launch --------------------------------------------------
extern "C" void kernel_launch(void* const* d_in, const int* in_sizes, int n_in,
                              void* d_out, int out_size) {
    const float* x     = (const float*)d_in[0];
    const float* Wq    = (const float*)d_in[1];
    const float* bq    = (const float*)d_in[2];
    const float* Wk    = (const float*)d_in[3];
    const float* bk    = (const float*)d_in[4];
    const float* Wv    = (const float*)d_in[5];
    const float* bv    = (const float*)d_in[6];
    const float* gamma = (const float*)d_in[7];
    float* out = (float*)d_out;

    const int sh1 = (CC * XST + CQ * KST + 64) * (int)sizeof(float);              // 83.2 KB
    const int sh2 = (CC * XST + CQ * KST + 64 + 64 + CC + CQ) * (int)sizeof(float); // 84.8 KB
    cudaFuncSetAttribute(k_pass1, cudaFuncAttributeMaxDynamicSharedMemorySize, sh1);
    cudaFuncSetAttribute(k_pass2, cudaFuncAttributeMaxDynamicSharedMemorySize, sh2);

    k_prep<<<256, 256>>>(Wq, Wk);
    k_pass1<<<BB * NTIL, 256, sh1>>>(x, bk);
    k_mat<<<BB, 256>>>(Wv, bv);
    k_pass2<<<BB * NTIL, 256, sh2>>>(x, bq, gamma, out);
}

// round 4
// speedup vs baseline: 1.2339x; 1.2339x over previous
#include <cuda_runtime.h>
#include <cstdint>

#define BB   8
#define CC   256
#define CQ   32
#define NN   16384
#define TN   128            // n per block
#define CH   32             // n per chunk
#define NCH  4
#define EPSV 1e-6f
#define ST   44             // tile row stride (floats); 44 mod 32 = 12 -> conflict-free frags

// ---------------- scratch (device globals) ---------------------------------
__device__ __align__(16) uint32_t g_WtF[4 * 32 * 32 * 4];   // tf32 A-frags; wo 0-1 = Wq, 2-3 = Wk
__device__ float g_mpT[BB * CC * CQ];                       // (Kn @ x^T)^T : [b][c][m]
__device__ float g_S[BB * CQ];                              // sum_n Kn
__device__ float g_xsum[BB * CC];                           // sum_n x
__device__ __align__(16) uint32_t g_mfrag[BB * 16 * 4 * 32 * 4]; // matT tf32 A-frags
__device__ float g_vsum[BB * CC];                           // value_sum

__device__ __forceinline__ uint32_t f2tf(float f) {
    uint32_t r; asm("cvt.rna.tf32.f32 %0, %1;" : "=r"(r) : "f"(f)); return r;
}

__device__ __forceinline__ void mma_tf32(float& d0, float& d1, float& d2, float& d3,
                                         uint32_t a0, uint32_t a1, uint32_t a2, uint32_t a3,
                                         uint32_t b0, uint32_t b1) {
    asm volatile(
        "mma.sync.aligned.m16n8k8.row.col.f32.tf32.tf32.f32 "
        "{%0,%1,%2,%3},{%4,%5,%6,%7},{%8,%9},{%0,%1,%2,%3};"
        : "+f"(d0), "+f"(d1), "+f"(d2), "+f"(d3)
        : "r"(a0), "r"(a1), "r"(a2), "r"(a3), "r"(b0), "r"(b1));
}

// ---------------- kernel 0: zero accumulators + build tf32 W-fragments -----
__global__ void k_prep(const float* __restrict__ Wq, const float* __restrict__ Wk) {
    int idx = blockIdx.x * blockDim.x + threadIdx.x;      // 65536 threads
    if (idx < BB * CC * CQ) g_mpT[idx] = 0.f;
    if (idx < 16384) {
        int f    = idx & 3;
        int lane = (idx >> 2) & 31;
        int kk   = (idx >> 7) & 31;
        int wo   = idx >> 12;
        int gid = lane >> 2, tig = lane & 3;
        int o = (wo & 1) * 16 + gid + (f & 1) * 8;
        int c = kk * 8 + tig + (f >> 1) * 4;
        float v = (wo < 2) ? Wq[o * CC + c] : Wk[o * CC + c];
        g_WtF[idx] = f2tf(v);
    }
    if (idx < BB * CC) g_xsum[idx] = 0.f;
    if (idx < BB * CQ) g_S[idx] = 0.f;
}

// ---------------- kernel 1: K pass: Kn, S, xsum, mpT (j-chunked) -----------
__global__ void __launch_bounds__(256, 4)
k_pass1(const float* __restrict__ x, const float* __restrict__ bk) {
    extern __shared__ float sh[];
    float* xs = sh;                       // [256][ST] x chunk (tf32 bits)
    float* kt = sh + CC * ST;             // [32][ST]  K -> Kn
    float* rn = kt + CQ * ST;             // [32]
    uint32_t* xsu = (uint32_t*)xs;
    uint32_t* ktu = (uint32_t*)kt;

    const int b   = blockIdx.x >> 7;
    const int n0  = (blockIdx.x & 127) * TN;
    const int tid = threadIdx.x;
    const int w = tid >> 5, lane = tid & 31, gid = lane >> 2, tig = lane & 3;
    const float* xb = x + (size_t)b * CC * NN;

    const int wo = w & 1, wj = w >> 1;
    const int o1 = 16 * wo + gid, o2 = o1 + 8;
    const float bi1 = __ldg(&bk[o1]), bi2 = __ldg(&bk[o2]);

    float e[2][4][4];
    #pragma unroll
    for (int ct = 0; ct < 2; ct++)
        #pragma unroll
        for (int mt = 0; mt < 4; mt++)
            #pragma unroll
            for (int q = 0; q < 4; q++) e[ct][mt][q] = 0.f;
    float xsum_acc = 0.f, S_acc = 0.f;

    for (int ch = 0; ch < NCH; ch++) {
        const int nb = n0 + ch * CH;

        // stage x chunk as tf32
        #pragma unroll
        for (int it = 0; it < 8; it++) {
            int idx = tid + it * 256;
            int c = idx >> 3, q = idx & 7;
            float4 v = *(const float4*)(xb + (size_t)c * NN + nb + 4 * q);
            uint4 t;
            t.x = f2tf(v.x); t.y = f2tf(v.y); t.z = f2tf(v.z); t.w = f2tf(v.w);
            *(uint4*)&xsu[c * ST + 4 * q] = t;
        }
        __syncthreads();

        // K[32o x 32j] = Wk @ chunk (full k = 256)
        {
            float d0 = 0.f, d1 = 0.f, d2 = 0.f, d3 = 0.f;
            const uint4* WtF = (const uint4*)g_WtF + ((2 + wo) * 32) * 32 + lane;
            #pragma unroll 4
            for (int kk = 0; kk < 32; kk++) {
                uint4 a = WtF[kk * 32];
                int c0 = kk * 8;
                uint32_t b0 = xsu[(c0 + tig) * ST + 8 * wj + gid];
                uint32_t b1 = xsu[(c0 + 4 + tig) * ST + 8 * wj + gid];
                mma_tf32(d0, d1, d2, d3, a.x, a.y, a.z, a.w, b0, b1);
            }
            int j = 8 * wj + 2 * tig;
            kt[o1 * ST + j]     = d0 + bi1;
            kt[o1 * ST + j + 1] = d1 + bi1;
            kt[o2 * ST + j]     = d2 + bi2;
            kt[o2 * ST + j + 1] = d3 + bi2;
        }
        __syncthreads();

        // norms (all warps, shfl reduce over 8-lane groups)
        {
            int j = 4 * w + (lane >> 3);
            int ob = (lane & 7) * 4;
            float s = 0.f;
            #pragma unroll
            for (int i = 0; i < 4; i++) { float v = kt[(ob + i) * ST + j]; s += v * v; }
            s += __shfl_xor_sync(0xffffffffu, s, 1, 8);
            s += __shfl_xor_sync(0xffffffffu, s, 2, 8);
            s += __shfl_xor_sync(0xffffffffu, s, 4, 8);
            if ((lane & 7) == 0) rn[j] = rsqrtf(s);
        }
        __syncthreads();

        // rescale K -> Kn (tf32) + S partial
        {
            int m = tid >> 3, jb = (tid & 7) * 4;
            float sl = 0.f;
            #pragma unroll
            for (int i = 0; i < 4; i++) {
                float v = kt[m * ST + jb + i] * rn[jb + i];
                sl += v;
                ktu[m * ST + jb + i] = f2tf(v);
            }
            sl += __shfl_xor_sync(0xffffffffu, sl, 1, 8);
            sl += __shfl_xor_sync(0xffffffffu, sl, 2, 8);
            sl += __shfl_xor_sync(0xffffffffu, sl, 4, 8);
            if ((tid & 7) == 0) S_acc += sl;
        }
        __syncthreads();

        // xsum partial (row tid)
        {
            float s = 0.f;
            #pragma unroll
            for (int q = 0; q < 8; q++) {
                uint4 v = *(uint4*)&xsu[tid * ST + 4 * q];
                s += __uint_as_float(v.x) + __uint_as_float(v.y)
                   + __uint_as_float(v.z) + __uint_as_float(v.w);
            }
            xsum_acc += s;
        }

        // mpT accumulate: e[c][m] += chunk @ Kn^T (k = 32)
        #pragma unroll
        for (int kk = 0; kk < 4; kk++) {
            int j0 = kk * 8;
            uint32_t bb0[4], bb1[4];
            #pragma unroll
            for (int mt = 0; mt < 4; mt++) {
                bb0[mt] = ktu[(mt * 8 + gid) * ST + j0 + tig];
                bb1[mt] = ktu[(mt * 8 + gid) * ST + j0 + 4 + tig];
            }
            #pragma unroll
            for (int ct = 0; ct < 2; ct++) {
                int c0 = (2 * w + ct) * 16;
                uint32_t a0 = xsu[(c0 + gid) * ST + j0 + tig];
                uint32_t a1 = xsu[(c0 + 8 + gid) * ST + j0 + tig];
                uint32_t a2 = xsu[(c0 + gid) * ST + j0 + 4 + tig];
                uint32_t a3 = xsu[(c0 + 8 + gid) * ST + j0 + 4 + tig];
                #pragma unroll
                for (int mt = 0; mt < 4; mt++)
                    mma_tf32(e[ct][mt][0], e[ct][mt][1], e[ct][mt][2], e[ct][mt][3],
                             a0, a1, a2, a3, bb0[mt], bb1[mt]);
            }
        }
        __syncthreads();   // protect xs/kt before next stage
    }

    // final reductions
    if ((tid & 7) == 0) atomicAdd(&g_S[b * CQ + (tid >> 3)], S_acc);
    atomicAdd(&g_xsum[b * CC + tid], xsum_acc);
    float* mpb = &g_mpT[b * CC * CQ];
    #pragma unroll
    for (int ct = 0; ct < 2; ct++) {
        int c0 = (2 * w + ct) * 16;
        #pragma unroll
        for (int mt = 0; mt < 4; mt++) {
            int m0 = mt * 8 + 2 * tig;
            atomicAdd(&mpb[(c0 + gid) * CQ + m0],         e[ct][mt][0]);
            atomicAdd(&mpb[(c0 + gid) * CQ + m0 + 1],     e[ct][mt][1]);
            atomicAdd(&mpb[(c0 + 8 + gid) * CQ + m0],     e[ct][mt][2]);
            atomicAdd(&mpb[(c0 + 8 + gid) * CQ + m0 + 1], e[ct][mt][3]);
        }
    }
}

// ---------------- kernel 2: matrix = mp @ Wv^T + bv (x) S ; vsum; fragments -
__global__ void __launch_bounds__(256)
k_mat(const float* __restrict__ Wv, const float* __restrict__ bv) {
    __shared__ float mpT[CC * CQ];   // [c][m]
    __shared__ float xs_s[CC];
    __shared__ float S_s[CQ];
    const int b = blockIdx.x, tid = threadIdx.x;

    for (int idx = tid; idx < CC * CQ; idx += 256)
        mpT[idx] = g_mpT[b * CC * CQ + idx];
    xs_s[tid] = g_xsum[b * CC + tid];
    if (tid < 32) S_s[tid] = g_S[b * CQ + tid];
    __syncthreads();

    const int cp = tid;
    float bvv = __ldg(&bv[cp]);
    float accm[32];
    #pragma unroll
    for (int m = 0; m < 32; m++) accm[m] = bvv * S_s[m];
    float vs = (float)NN * bvv;

    const float* wrow = Wv + cp * CC;
    for (int c = 0; c < CC; ++c) {
        float wv = __ldg(&wrow[c]);
        vs += wv * xs_s[c];
        const float4* mr = (const float4*)&mpT[c * CQ];
        #pragma unroll
        for (int q = 0; q < 8; q++) {
            float4 v = mr[q];
            accm[q * 4 + 0] += v.x * wv; accm[q * 4 + 1] += v.y * wv;
            accm[q * 4 + 2] += v.z * wv; accm[q * 4 + 3] += v.w * wv;
        }
    }
    g_vsum[b * CC + cp] = vs;

    const int ct = cp >> 4, cl = cp & 15;
    const int gid = cl & 7, hi = cl >> 3;
    #pragma unroll
    for (int m = 0; m < 32; m++) {
        int kk = m >> 3, tig = m & 3, half = (m >> 2) & 1;
        int elem = hi + 2 * half;
        g_mfrag[((((b * 16 + ct) * 4 + kk) * 32) + gid * 4 + tig) * 4 + elem] = f2tf(accm[m]);
    }
}

// ---------------- kernel 3: Q pass + TC epilogue (j-chunked) ----------------
__global__ void __launch_bounds__(256, 4)
k_pass2(const float* __restrict__ x, const float* __restrict__ bq,
        const float* __restrict__ gamma, float* __restrict__ out) {
    extern __shared__ float sh[];
    float* xs   = sh;                     // [256][ST] x chunk fp32 (residual!)
    float* qt   = sh + CC * ST;           // [32][ST]  Q -> Qn
    float* rn   = qt + CQ * ST;           // [32]
    float* gt   = rn + CQ;                // [32]
    float* vs_s = gt + CQ;                // [256]
    float* Se   = vs_s + CC;              // [32]
    uint32_t* qtu = (uint32_t*)qt;

    const int b   = blockIdx.x >> 7;
    const int n0  = (blockIdx.x & 127) * TN;
    const int tid = threadIdx.x;
    const int w = tid >> 5, lane = tid & 31, gid = lane >> 2, tig = lane & 3;
    const float* xb = x + (size_t)b * CC * NN;
    float* ob = out + (size_t)b * CC * NN;

    const int wo = w & 1, wj = w >> 1;
    const int o1 = 16 * wo + gid, o2 = o1 + 8;
    const float bi1 = __ldg(&bq[o1]), bi2 = __ldg(&bq[o2]);
    const float gm = __ldg(&gamma[0]);

    vs_s[tid] = g_vsum[b * CC + tid];
    if (tid < 32) Se[tid] = g_S[b * CQ + tid] + EPSV;

    for (int ch = 0; ch < NCH; ch++) {
        const int nb = n0 + ch * CH;

        // stage x chunk fp32
        #pragma unroll
        for (int it = 0; it < 8; it++) {
            int idx = tid + it * 256;
            int c = idx >> 3, q = idx & 7;
            *(float4*)&xs[c * ST + 4 * q] =
                *(const float4*)(xb + (size_t)c * NN + nb + 4 * q);
        }
        __syncthreads();

        // Q[32o x 32j] = Wq @ chunk (cvt B on read)
        {
            float d0 = 0.f, d1 = 0.f, d2 = 0.f, d3 = 0.f;
            const uint4* WtF = (const uint4*)g_WtF + (wo * 32) * 32 + lane;
            #pragma unroll 4
            for (int kk = 0; kk < 32; kk++) {
                uint4 a = WtF[kk * 32];
                int c0 = kk * 8;
                uint32_t b0 = f2tf(xs[(c0 + tig) * ST + 8 * wj + gid]);
                uint32_t b1 = f2tf(xs[(c0 + 4 + tig) * ST + 8 * wj + gid]);
                mma_tf32(d0, d1, d2, d3, a.x, a.y, a.z, a.w, b0, b1);
            }
            int j = 8 * wj + 2 * tig;
            qt[o1 * ST + j]     = d0 + bi1;
            qt[o1 * ST + j + 1] = d1 + bi1;
            qt[o2 * ST + j]     = d2 + bi2;
            qt[o2 * ST + j + 1] = d3 + bi2;
        }
        __syncthreads();

        // norms
        {
            int j = 4 * w + (lane >> 3);
            int obs = (lane & 7) * 4;
            float s = 0.f;
            #pragma unroll
            for (int i = 0; i < 4; i++) { float v = qt[(obs + i) * ST + j]; s += v * v; }
            s += __shfl_xor_sync(0xffffffffu, s, 1, 8);
            s += __shfl_xor_sync(0xffffffffu, s, 2, 8);
            s += __shfl_xor_sync(0xffffffffu, s, 4, 8);
            if ((lane & 7) == 0) rn[j] = rsqrtf(s);
        }
        __syncthreads();

        // rescale Q -> Qn (tf32)
        {
            int m = tid >> 3, jb = (tid & 7) * 4;
            #pragma unroll
            for (int i = 0; i < 4; i++) {
                float v = qt[m * ST + jb + i] * rn[jb + i];
                qtu[m * ST + jb + i] = f2tf(v);
            }
        }
        __syncthreads();

        // tailor -> gt[j]
        {
            int j = 4 * w + (lane >> 3);
            int m0 = lane & 7;
            float tl = 0.f;
            #pragma unroll
            for (int i = 0; i < 4; i++) {
                int m = m0 + 8 * i;
                tl += __uint_as_float(qtu[m * ST + j]) * Se[m];
            }
            tl += __shfl_xor_sync(0xffffffffu, tl, 1, 8);
            tl += __shfl_xor_sync(0xffffffffu, tl, 2, 8);
            tl += __shfl_xor_sync(0xffffffffu, tl, 4, 8);
            if ((lane & 7) == 0) gt[j] = gm / ((float)NN + tl);
        }
        __syncthreads();

        // D = matT @ Qn, fused epilogue + store
        {
            uint4 A[2][4];
            #pragma unroll
            for (int ct = 0; ct < 2; ct++)
                #pragma unroll
                for (int kk = 0; kk < 4; kk++)
                    A[ct][kk] = *((const uint4*)g_mfrag +
                                  ((b * 16 + 2 * w + ct) * 4 + kk) * 32 + lane);

            #pragma unroll
            for (int jt = 0; jt < 4; jt++) {
                uint32_t B0[4], B1[4];
                #pragma unroll
                for (int kk = 0; kk < 4; kk++) {
                    B0[kk] = qtu[(kk * 8 + tig) * ST + jt * 8 + gid];
                    B1[kk] = qtu[(kk * 8 + 4 + tig) * ST + jt * 8 + gid];
                }
                const int j = jt * 8 + 2 * tig;
                const float gt0 = gt[j], gt1 = gt[j + 1];
                #pragma unroll
                for (int ct = 0; ct < 2; ct++) {
                    float e0 = 0.f, e1 = 0.f, e2 = 0.f, e3 = 0.f;
                    #pragma unroll
                    for (int kk = 0; kk < 4; kk++)
                        mma_tf32(e0, e1, e2, e3,
                                 A[ct][kk].x, A[ct][kk].y, A[ct][kk].z, A[ct][kk].w,
                                 B0[kk], B1[kk]);
                    const int c1 = (2 * w + ct) * 16 + gid;
                    const int c2 = c1 + 8;
                    float2 o1v, o2v;
                    o1v.x = xs[c1 * ST + j]     + gt0 * (vs_s[c1] + e0);
                    o1v.y = xs[c1 * ST + j + 1] + gt1 * (vs_s[c1] + e1);
                    o2v.x = xs[c2 * ST + j]     + gt0 * (vs_s[c2] + e2);
                    o2v.y = xs[c2 * ST + j + 1] + gt1 * (vs_s[c2] + e3);
                    *(float2*)(ob + (size_t)c1 * NN + nb + j) = o1v;
                    *(float2*)(ob + (size_t)c2 * NN + nb + j) = o2v;
                }
            }
        }
        __syncthreads();
    }
}

// ---------------- launch --------------------------------------------------
extern "C" void kernel_launch(void* const* d_in, const int* in_sizes, int n_in,
                              void* d_out, int out_size) {
    const float* x     = (const float*)d_in[0];
    const float* Wq    = (const float*)d_in[1];
    const float* bq    = (const float*)d_in[2];
    const float* Wk    = (const float*)d_in[3];
    const float* bk    = (const float*)d_in[4];
    const float* Wv    = (const float*)d_in[5];
    const float* bv    = (const float*)d_in[6];
    const float* gamma = (const float*)d_in[7];
    float* out = (float*)d_out;

    const int sh1 = (CC * ST + CQ * ST + CQ) * (int)sizeof(float);                       // 50816 B
    const int sh2 = (CC * ST + CQ * ST + CQ + CQ + CC + CQ) * (int)sizeof(float);        // 52096 B
    cudaFuncSetAttribute(k_pass1, cudaFuncAttributeMaxDynamicSharedMemorySize, sh1);
    cudaFuncSetAttribute(k_pass2, cudaFuncAttributeMaxDynamicSharedMemorySize, sh2);

    k_prep<<<256, 256>>>(Wq, Wk);
    k_pass1<<<BB * (NN / TN), 256, sh1>>>(x, bk);
    k_mat<<<BB, 256>>>(Wv, bv);
    k_pass2<<<BB * (NN / TN), 256, sh2>>>(x, bq, gamma, out);
}

// round 5
// speedup vs baseline: 1.3345x; 1.0815x over previous
#include <cuda_runtime.h>
#include <cstdint>

#define BB   8
#define CC   256
#define CQ   32
#define NN   16384
#define TN   128            // n per block
#define CH   32             // n per chunk
#define NCH  4
#define EPSV 1e-6f
#define ST   44             // tile row stride; 44 mod 32 = 12 -> conflict-free frag loads

// ---------------- scratch (device globals) ---------------------------------
__device__ __align__(16) uint32_t g_WtF[4 * 32 * 32 * 4];   // tf32 A-frags; wo 0-1 = Wq, 2-3 = Wk
__device__ float g_mpT[BB * CC * CQ];                       // (Kn @ x^T)^T : [b][c][m]
__device__ float g_S[BB * CQ];                              // sum_n Kn
__device__ float g_xsum[BB * CC];                           // sum_n x
__device__ __align__(16) uint32_t g_mfrag[BB * 16 * 4 * 32 * 4]; // matT tf32 A-frags
__device__ float g_vsum[BB * CC];                           // value_sum

__device__ __forceinline__ uint32_t f2tf(float f) {
    uint32_t r; asm("cvt.rna.tf32.f32 %0, %1;" : "=r"(r) : "f"(f)); return r;
}

__device__ __forceinline__ void mma_tf32(float& d0, float& d1, float& d2, float& d3,
                                         uint32_t a0, uint32_t a1, uint32_t a2, uint32_t a3,
                                         uint32_t b0, uint32_t b1) {
    asm volatile(
        "mma.sync.aligned.m16n8k8.row.col.f32.tf32.tf32.f32 "
        "{%0,%1,%2,%3},{%4,%5,%6,%7},{%8,%9},{%0,%1,%2,%3};"
        : "+f"(d0), "+f"(d1), "+f"(d2), "+f"(d3)
        : "r"(a0), "r"(a1), "r"(a2), "r"(a3), "r"(b0), "r"(b1));
}

__device__ __forceinline__ void cp16(float* dst, const float* src) {
    uint32_t d = (uint32_t)__cvta_generic_to_shared(dst);
    asm volatile("cp.async.cg.shared.global [%0], [%1], 16;" :: "r"(d), "l"(src));
}
__device__ __forceinline__ void cp_commit() {
    asm volatile("cp.async.commit_group;");
}
__device__ __forceinline__ void cp_wait0() {
    asm volatile("cp.async.wait_group 0;");
}

// issue one chunk stage: 8 x 16B per thread
__device__ __forceinline__ void stage_issue(float* xs, const float* xb, int nb, int tid) {
    #pragma unroll
    for (int it = 0; it < 8; it++) {
        int idx = tid + it * 256;
        int c = idx >> 3, q = idx & 7;
        cp16(&xs[c * ST + 4 * q], xb + (size_t)c * NN + nb + 4 * q);
    }
}

// ---------------- kernel 0: zero accumulators + build tf32 W-fragments -----
__global__ void k_prep(const float* __restrict__ Wq, const float* __restrict__ Wk) {
    int idx = blockIdx.x * blockDim.x + threadIdx.x;      // 65536 threads
    if (idx < BB * CC * CQ) g_mpT[idx] = 0.f;
    if (idx < 16384) {
        int f    = idx & 3;
        int lane = (idx >> 2) & 31;
        int kk   = (idx >> 7) & 31;
        int wo   = idx >> 12;
        int gid = lane >> 2, tig = lane & 3;
        int o = (wo & 1) * 16 + gid + (f & 1) * 8;
        int c = kk * 8 + tig + (f >> 1) * 4;
        float v = (wo < 2) ? Wq[o * CC + c] : Wk[o * CC + c];
        g_WtF[idx] = f2tf(v);
    }
    if (idx < BB * CC) g_xsum[idx] = 0.f;
    if (idx < BB * CQ) g_S[idx] = 0.f;
}

// ---------------- kernel 1: K pass: Kn, S, xsum, mpT (cp.async pipelined) ---
__global__ void __launch_bounds__(256, 2)
k_pass1(const float* __restrict__ x, const float* __restrict__ bk) {
    extern __shared__ float sh[];
    float* xsb[2] = { sh, sh + CC * ST };
    float* kt = sh + 2 * CC * ST;         // [32][ST]  K -> Kn(tf32)
    float* rn = kt + CQ * ST;             // [32]
    uint32_t* ktu = (uint32_t*)kt;

    const int b   = blockIdx.x >> 7;
    const int n0  = (blockIdx.x & 127) * TN;
    const int tid = threadIdx.x;
    const int w = tid >> 5, lane = tid & 31, gid = lane >> 2, tig = lane & 3;
    const float* xb = x + (size_t)b * CC * NN;

    const int wo = w & 1, wj = w >> 1;
    const int o1 = 16 * wo + gid, o2 = o1 + 8;
    const float bi1 = __ldg(&bk[o1]), bi2 = __ldg(&bk[o2]);

    float e[2][4][4];
    #pragma unroll
    for (int ct = 0; ct < 2; ct++)
        #pragma unroll
        for (int mt = 0; mt < 4; mt++)
            #pragma unroll
            for (int q = 0; q < 4; q++) e[ct][mt][q] = 0.f;
    float xsum_acc = 0.f, S_acc = 0.f;

    stage_issue(xsb[0], xb, n0, tid);
    cp_commit();

    for (int ch = 0; ch < NCH; ch++) {
        cp_wait0();
        __syncthreads();                 // data visible + kt reuse protected
        if (ch + 1 < NCH) {
            stage_issue(xsb[(ch + 1) & 1], xb, n0 + (ch + 1) * CH, tid);
            cp_commit();
        }
        const float* xs = xsb[ch & 1];

        // K[32o x 32j] = Wk @ chunk (k = 256), cvt B on read
        {
            float d0 = 0.f, d1 = 0.f, d2 = 0.f, d3 = 0.f;
            const uint4* WtF = (const uint4*)g_WtF + ((2 + wo) * 32) * 32 + lane;
            #pragma unroll 4
            for (int kk = 0; kk < 32; kk++) {
                uint4 a = WtF[kk * 32];
                int c0 = kk * 8;
                uint32_t b0 = f2tf(xs[(c0 + tig) * ST + 8 * wj + gid]);
                uint32_t b1 = f2tf(xs[(c0 + 4 + tig) * ST + 8 * wj + gid]);
                mma_tf32(d0, d1, d2, d3, a.x, a.y, a.z, a.w, b0, b1);
            }
            int j = 8 * wj + 2 * tig;
            kt[o1 * ST + j]     = d0 + bi1;
            kt[o1 * ST + j + 1] = d1 + bi1;
            kt[o2 * ST + j]     = d2 + bi2;
            kt[o2 * ST + j + 1] = d3 + bi2;
        }
        __syncthreads();

        // column norms
        {
            int j = 4 * w + (lane >> 3);
            int ob = (lane & 7) * 4;
            float s = 0.f;
            #pragma unroll
            for (int i = 0; i < 4; i++) { float v = kt[(ob + i) * ST + j]; s += v * v; }
            s += __shfl_xor_sync(0xffffffffu, s, 1, 8);
            s += __shfl_xor_sync(0xffffffffu, s, 2, 8);
            s += __shfl_xor_sync(0xffffffffu, s, 4, 8);
            if ((lane & 7) == 0) rn[j] = rsqrtf(s);
        }
        __syncthreads();

        // rescale K -> Kn (tf32) + S partial
        {
            int m = tid >> 3, jb = (tid & 7) * 4;
            float sl = 0.f;
            #pragma unroll
            for (int i = 0; i < 4; i++) {
                float v = kt[m * ST + jb + i] * rn[jb + i];
                sl += v;
                ktu[m * ST + jb + i] = f2tf(v);
            }
            sl += __shfl_xor_sync(0xffffffffu, sl, 1, 8);
            sl += __shfl_xor_sync(0xffffffffu, sl, 2, 8);
            sl += __shfl_xor_sync(0xffffffffu, sl, 4, 8);
            if ((tid & 7) == 0) S_acc += sl;
        }
        __syncthreads();

        // xsum partial (exact fp32)
        {
            float s = 0.f;
            #pragma unroll
            for (int q = 0; q < 8; q++) {
                float4 v = *(const float4*)&xs[tid * ST + 4 * q];
                s += v.x + v.y + v.z + v.w;
            }
            xsum_acc += s;
        }

        // mpT accumulate: e[c][m] += chunk @ Kn^T (k = 32), cvt A on read
        #pragma unroll
        for (int kk = 0; kk < 4; kk++) {
            int j0 = kk * 8;
            uint32_t bb0[4], bb1[4];
            #pragma unroll
            for (int mt = 0; mt < 4; mt++) {
                bb0[mt] = ktu[(mt * 8 + gid) * ST + j0 + tig];
                bb1[mt] = ktu[(mt * 8 + gid) * ST + j0 + 4 + tig];
            }
            #pragma unroll
            for (int ct = 0; ct < 2; ct++) {
                int c0 = (2 * w + ct) * 16;
                uint32_t a0 = f2tf(xs[(c0 + gid) * ST + j0 + tig]);
                uint32_t a1 = f2tf(xs[(c0 + 8 + gid) * ST + j0 + tig]);
                uint32_t a2 = f2tf(xs[(c0 + gid) * ST + j0 + 4 + tig]);
                uint32_t a3 = f2tf(xs[(c0 + 8 + gid) * ST + j0 + 4 + tig]);
                #pragma unroll
                for (int mt = 0; mt < 4; mt++)
                    mma_tf32(e[ct][mt][0], e[ct][mt][1], e[ct][mt][2], e[ct][mt][3],
                             a0, a1, a2, a3, bb0[mt], bb1[mt]);
            }
        }
        // no end sync: next top sync protects kt
    }

    // final reductions
    if ((tid & 7) == 0) atomicAdd(&g_S[b * CQ + (tid >> 3)], S_acc);
    atomicAdd(&g_xsum[b * CC + tid], xsum_acc);
    float* mpb = &g_mpT[b * CC * CQ];
    #pragma unroll
    for (int ct = 0; ct < 2; ct++) {
        int c0 = (2 * w + ct) * 16;
        #pragma unroll
        for (int mt = 0; mt < 4; mt++) {
            int m0 = mt * 8 + 2 * tig;
            atomicAdd(&mpb[(c0 + gid) * CQ + m0],         e[ct][mt][0]);
            atomicAdd(&mpb[(c0 + gid) * CQ + m0 + 1],     e[ct][mt][1]);
            atomicAdd(&mpb[(c0 + 8 + gid) * CQ + m0],     e[ct][mt][2]);
            atomicAdd(&mpb[(c0 + 8 + gid) * CQ + m0 + 1], e[ct][mt][3]);
        }
    }
}

// ---------------- kernel 2: matrix = mp @ Wv^T + bv (x) S ; vsum; fragments -
__global__ void __launch_bounds__(256)
k_mat(const float* __restrict__ Wv, const float* __restrict__ bv) {
    __shared__ float mpT[CC * CQ];   // [c][m]
    __shared__ float xs_s[CC];
    __shared__ float S_s[CQ];
    const int b = blockIdx.x, tid = threadIdx.x;

    for (int idx = tid; idx < CC * CQ; idx += 256)
        mpT[idx] = g_mpT[b * CC * CQ + idx];
    xs_s[tid] = g_xsum[b * CC + tid];
    if (tid < 32) S_s[tid] = g_S[b * CQ + tid];
    __syncthreads();

    const int cp = tid;
    float bvv = __ldg(&bv[cp]);
    float accm[32];
    #pragma unroll
    for (int m = 0; m < 32; m++) accm[m] = bvv * S_s[m];
    float vs = (float)NN * bvv;

    const float* wrow = Wv + cp * CC;
    for (int c = 0; c < CC; ++c) {
        float wv = __ldg(&wrow[c]);
        vs += wv * xs_s[c];
        const float4* mr = (const float4*)&mpT[c * CQ];
        #pragma unroll
        for (int q = 0; q < 8; q++) {
            float4 v = mr[q];
            accm[q * 4 + 0] += v.x * wv; accm[q * 4 + 1] += v.y * wv;
            accm[q * 4 + 2] += v.z * wv; accm[q * 4 + 3] += v.w * wv;
        }
    }
    g_vsum[b * CC + cp] = vs;

    const int ct = cp >> 4, cl = cp & 15;
    const int gid = cl & 7, hi = cl >> 3;
    #pragma unroll
    for (int m = 0; m < 32; m++) {
        int kk = m >> 3, tig = m & 3, half = (m >> 2) & 1;
        int elem = hi + 2 * half;
        g_mfrag[((((b * 16 + ct) * 4 + kk) * 32) + gid * 4 + tig) * 4 + elem] = f2tf(accm[m]);
    }
}

// ---------------- kernel 3: Q pass + TC epilogue (cp.async pipelined) -------
__global__ void __launch_bounds__(256, 2)
k_pass2(const float* __restrict__ x, const float* __restrict__ bq,
        const float* __restrict__ gamma, float* __restrict__ out) {
    extern __shared__ float sh[];
    float* xsb[2] = { sh, sh + CC * ST };
    float* qt   = sh + 2 * CC * ST;       // [32][ST] Q -> Qn(tf32)
    float* rn   = qt + CQ * ST;           // [32]
    float* gt   = rn + CQ;                // [32]
    float* vs_s = gt + CQ;                // [256]
    float* Se   = vs_s + CC;              // [32]
    uint32_t* qtu = (uint32_t*)qt;

    const int b   = blockIdx.x >> 7;
    const int n0  = (blockIdx.x & 127) * TN;
    const int tid = threadIdx.x;
    const int w = tid >> 5, lane = tid & 31, gid = lane >> 2, tig = lane & 3;
    const float* xb = x + (size_t)b * CC * NN;
    float* ob = out + (size_t)b * CC * NN;

    const int wo = w & 1, wj = w >> 1;
    const int o1 = 16 * wo + gid, o2 = o1 + 8;
    const float bi1 = __ldg(&bq[o1]), bi2 = __ldg(&bq[o2]);
    const float gm = __ldg(&gamma[0]);

    stage_issue(xsb[0], xb, n0, tid);
    cp_commit();

    vs_s[tid] = g_vsum[b * CC + tid];
    if (tid < 32) Se[tid] = g_S[b * CQ + tid] + EPSV;

    // hoisted matT A-fragments
    uint4 A[2][4];
    #pragma unroll
    for (int ct = 0; ct < 2; ct++)
        #pragma unroll
        for (int kk = 0; kk < 4; kk++)
            A[ct][kk] = *((const uint4*)g_mfrag +
                          ((b * 16 + 2 * w + ct) * 4 + kk) * 32 + lane);

    for (int ch = 0; ch < NCH; ch++) {
        const int nb = n0 + ch * CH;
        cp_wait0();
        __syncthreads();
        if (ch + 1 < NCH) {
            stage_issue(xsb[(ch + 1) & 1], xb, n0 + (ch + 1) * CH, tid);
            cp_commit();
        }
        const float* xs = xsb[ch & 1];

        // Q[32o x 32j] = Wq @ chunk (cvt B on read)
        {
            float d0 = 0.f, d1 = 0.f, d2 = 0.f, d3 = 0.f;
            const uint4* WtF = (const uint4*)g_WtF + (wo * 32) * 32 + lane;
            #pragma unroll 4
            for (int kk = 0; kk < 32; kk++) {
                uint4 a = WtF[kk * 32];
                int c0 = kk * 8;
                uint32_t b0 = f2tf(xs[(c0 + tig) * ST + 8 * wj + gid]);
                uint32_t b1 = f2tf(xs[(c0 + 4 + tig) * ST + 8 * wj + gid]);
                mma_tf32(d0, d1, d2, d3, a.x, a.y, a.z, a.w, b0, b1);
            }
            int j = 8 * wj + 2 * tig;
            qt[o1 * ST + j]     = d0 + bi1;
            qt[o1 * ST + j + 1] = d1 + bi1;
            qt[o2 * ST + j]     = d2 + bi2;
            qt[o2 * ST + j + 1] = d3 + bi2;
        }
        __syncthreads();

        // merged column reductions: ||Q||^2 and Q.(S+eps) -> rn, gt
        {
            int j = 4 * w + (lane >> 3);
            int obs = (lane & 7) * 4;
            float s = 0.f, t = 0.f;
            #pragma unroll
            for (int i = 0; i < 4; i++) {
                float v = qt[(obs + i) * ST + j];
                s += v * v;
                t += v * Se[obs + i];
            }
            s += __shfl_xor_sync(0xffffffffu, s, 1, 8);
            s += __shfl_xor_sync(0xffffffffu, s, 2, 8);
            s += __shfl_xor_sync(0xffffffffu, s, 4, 8);
            t += __shfl_xor_sync(0xffffffffu, t, 1, 8);
            t += __shfl_xor_sync(0xffffffffu, t, 2, 8);
            t += __shfl_xor_sync(0xffffffffu, t, 4, 8);
            if ((lane & 7) == 0) {
                float r = rsqrtf(s);
                rn[j] = r;
                gt[j] = gm / ((float)NN + r * t);
            }
        }
        __syncthreads();

        // rescale Q -> Qn (tf32)
        {
            int m = tid >> 3, jb = (tid & 7) * 4;
            #pragma unroll
            for (int i = 0; i < 4; i++) {
                float v = qt[m * ST + jb + i] * rn[jb + i];
                qtu[m * ST + jb + i] = f2tf(v);
            }
        }
        __syncthreads();

        // D = matT @ Qn, fused epilogue + store
        #pragma unroll
        for (int jt = 0; jt < 4; jt++) {
            uint32_t B0[4], B1[4];
            #pragma unroll
            for (int kk = 0; kk < 4; kk++) {
                B0[kk] = qtu[(kk * 8 + tig) * ST + jt * 8 + gid];
                B1[kk] = qtu[(kk * 8 + 4 + tig) * ST + jt * 8 + gid];
            }
            const int j = jt * 8 + 2 * tig;
            const float gt0 = gt[j], gt1 = gt[j + 1];
            #pragma unroll
            for (int ct = 0; ct < 2; ct++) {
                float e0 = 0.f, e1 = 0.f, e2 = 0.f, e3 = 0.f;
                #pragma unroll
                for (int kk = 0; kk < 4; kk++)
                    mma_tf32(e0, e1, e2, e3,
                             A[ct][kk].x, A[ct][kk].y, A[ct][kk].z, A[ct][kk].w,
                             B0[kk], B1[kk]);
                const int c1 = (2 * w + ct) * 16 + gid;
                const int c2 = c1 + 8;
                float2 o1v, o2v;
                o1v.x = xs[c1 * ST + j]     + gt0 * (vs_s[c1] + e0);
                o1v.y = xs[c1 * ST + j + 1] + gt1 * (vs_s[c1] + e1);
                o2v.x = xs[c2 * ST + j]     + gt0 * (vs_s[c2] + e2);
                o2v.y = xs[c2 * ST + j + 1] + gt1 * (vs_s[c2] + e3);
                *(float2*)(ob + (size_t)c1 * NN + nb + j) = o1v;
                *(float2*)(ob + (size_t)c2 * NN + nb + j) = o2v;
            }
        }
        // no end sync: next top sync protects qt
    }
}

// ---------------- launch --------------------------------------------------
extern "C" void kernel_launch(void* const* d_in, const int* in_sizes, int n_in,
                              void* d_out, int out_size) {
    const float* x     = (const float*)d_in[0];
    const float* Wq    = (const float*)d_in[1];
    const float* bq    = (const float*)d_in[2];
    const float* Wk    = (const float*)d_in[3];
    const float* bk    = (const float*)d_in[4];
    const float* Wv    = (const float*)d_in[5];
    const float* bv    = (const float*)d_in[6];
    const float* gamma = (const float*)d_in[7];
    float* out = (float*)d_out;

    const int sh1 = (2 * CC * ST + CQ * ST + CQ) * (int)sizeof(float);                 // 95,872 B
    const int sh2 = (2 * CC * ST + CQ * ST + CQ + CQ + CC + CQ) * (int)sizeof(float);  // 97,152 B
    cudaFuncSetAttribute(k_pass1, cudaFuncAttributeMaxDynamicSharedMemorySize, sh1);
    cudaFuncSetAttribute(k_pass2, cudaFuncAttributeMaxDynamicSharedMemorySize, sh2);

    k_prep<<<256, 256>>>(Wq, Wk);
    k_pass1<<<BB * (NN / TN), 256, sh1>>>(x, bk);
    k_mat<<<BB, 256>>>(Wv, bv);
    k_pass2<<<BB * (NN / TN), 256, sh2>>>(x, bq, gamma, out);
}

// round 6
// speedup vs baseline: 1.4513x; 1.0875x over previous
#include <cuda_runtime.h>
#include <cstdint>

#define BB   8
#define CC   256
#define CQ   32
#define NN   16384
#define EPSV 1e-6f
#define STX  72             // xs stride; 72 mod 32 = 8 -> pattern-1 (B-frag) conflict-free
#define STK  76             // kt stride; 76 mod 32 = 12 -> pattern-2 (B-frag mpT) conflict-free
#define T1   256            // pass1 n per block (4 subtiles of 64)
#define SUB  64             // subtile width
#define T2   64             // pass2 n per block

// ---------------- scratch (device globals) ---------------------------------
__device__ __align__(16) uint32_t g_WtF[4 * 32 * 32 * 4];   // tf32 A-frags; wo 0-1 = Wq, 2-3 = Wk
__device__ float g_mpT[BB * CC * CQ];                       // (Kn @ x^T)^T : [b][c][m]
__device__ float g_S[BB * CQ];                              // sum_n Kn
__device__ float g_xsum[BB * CC];                           // sum_n x
__device__ __align__(16) uint32_t g_mfrag[BB * 16 * 4 * 32 * 4]; // matT tf32 A-frags
__device__ float g_vsum[BB * CC];                           // value_sum

__device__ __forceinline__ uint32_t f2tf(float f) {
    uint32_t r; asm("cvt.rna.tf32.f32 %0, %1;" : "=r"(r) : "f"(f)); return r;
}

__device__ __forceinline__ void mma_tf32(float& d0, float& d1, float& d2, float& d3,
                                         uint32_t a0, uint32_t a1, uint32_t a2, uint32_t a3,
                                         uint32_t b0, uint32_t b1) {
    asm volatile(
        "mma.sync.aligned.m16n8k8.row.col.f32.tf32.tf32.f32 "
        "{%0,%1,%2,%3},{%4,%5,%6,%7},{%8,%9},{%0,%1,%2,%3};"
        : "+f"(d0), "+f"(d1), "+f"(d2), "+f"(d3)
        : "r"(a0), "r"(a1), "r"(a2), "r"(a3), "r"(b0), "r"(b1));
}

__device__ __forceinline__ void cp16(float* dst, const float* src) {
    uint32_t d = (uint32_t)__cvta_generic_to_shared(dst);
    asm volatile("cp.async.cg.shared.global [%0], [%1], 16;" :: "r"(d), "l"(src));
}
__device__ __forceinline__ void cp_commit() { asm volatile("cp.async.commit_group;"); }
__device__ __forceinline__ void cp_wait0()  { asm volatile("cp.async.wait_group 0;"); }

// stage one 64-j x tile (256 c x 64 j, fp32): 16 x 16B per thread
__device__ __forceinline__ void stage_issue(float* xs, const float* xb, int nb, int tid) {
    #pragma unroll
    for (int it = 0; it < 16; it++) {
        int idx = tid + it * 256;
        int c = idx >> 4, q = idx & 15;
        cp16(&xs[c * STX + 4 * q], xb + (size_t)c * NN + nb + 4 * q);
    }
}

// ---------------- kernel 0: zero accumulators + build tf32 W-fragments -----
__global__ void k_prep(const float* __restrict__ Wq, const float* __restrict__ Wk) {
    int idx = blockIdx.x * blockDim.x + threadIdx.x;      // 65536 threads
    if (idx < BB * CC * CQ) g_mpT[idx] = 0.f;
    if (idx < 16384) {
        int f    = idx & 3;
        int lane = (idx >> 2) & 31;
        int kk   = (idx >> 7) & 31;
        int wo   = idx >> 12;
        int gid = lane >> 2, tig = lane & 3;
        int o = (wo & 1) * 16 + gid + (f & 1) * 8;
        int c = kk * 8 + tig + (f >> 1) * 4;
        float v = (wo < 2) ? Wq[o * CC + c] : Wk[o * CC + c];
        g_WtF[idx] = f2tf(v);
    }
    if (idx < BB * CC) g_xsum[idx] = 0.f;
    if (idx < BB * CQ) g_S[idx] = 0.f;
}

// ---------------- kernel 1: K pass (warp-autonomous proj, TN=256) ----------
__global__ void __launch_bounds__(256, 2)
k_pass1(const float* __restrict__ x, const float* __restrict__ bk) {
    extern __shared__ float sh[];
    float* xs = sh;                       // [256][STX] fp32 x subtile
    float* kt = sh + CC * STX;            // [32][STK]  Kn (tf32 bits)
    uint32_t* ktu = (uint32_t*)kt;

    const int b   = blockIdx.x >> 6;
    const int n0  = (blockIdx.x & 63) * T1;
    const int tid = threadIdx.x;
    const int w = tid >> 5, lane = tid & 31, gid = lane >> 2, tig = lane & 3;
    const int jw = w * 8;
    const float* xb = x + (size_t)b * CC * NN;

    const float bk0 = __ldg(&bk[gid]);
    const float bk1 = __ldg(&bk[gid + 8]);
    const float bk2 = __ldg(&bk[gid + 16]);
    const float bk3 = __ldg(&bk[gid + 24]);

    float e[2][4][4];
    #pragma unroll
    for (int ct = 0; ct < 2; ct++)
        #pragma unroll
        for (int mt = 0; mt < 4; mt++)
            #pragma unroll
            for (int q = 0; q < 4; q++) e[ct][mt][q] = 0.f;
    float xsum_acc = 0.f, S_acc = 0.f;

    stage_issue(xs, xb, n0, tid);
    cp_commit();

    for (int ch = 0; ch < 4; ch++) {
        cp_wait0();
        __syncthreads();                         // xs ready; kt free

        // ---- warp-local: K proj for own 8 j (k = 256) ----
        float d[2][4];
        #pragma unroll
        for (int wo = 0; wo < 2; wo++)
            #pragma unroll
            for (int q = 0; q < 4; q++) d[wo][q] = 0.f;
        {
            const uint4* W0 = (const uint4*)g_WtF + 2 * 1024 + lane;
            const uint4* W1 = (const uint4*)g_WtF + 3 * 1024 + lane;
            #pragma unroll 4
            for (int kk = 0; kk < 32; kk++) {
                int c0 = kk * 8;
                uint32_t b0 = f2tf(xs[(c0 + tig) * STX + jw + gid]);
                uint32_t b1 = f2tf(xs[(c0 + 4 + tig) * STX + jw + gid]);
                uint4 a0 = W0[kk * 32];
                mma_tf32(d[0][0], d[0][1], d[0][2], d[0][3], a0.x, a0.y, a0.z, a0.w, b0, b1);
                uint4 a1 = W1[kk * 32];
                mma_tf32(d[1][0], d[1][1], d[1][2], d[1][3], a1.x, a1.y, a1.z, a1.w, b0, b1);
            }
        }
        d[0][0] += bk0; d[0][1] += bk0; d[0][2] += bk1; d[0][3] += bk1;
        d[1][0] += bk2; d[1][1] += bk2; d[1][2] += bk3; d[1][3] += bk3;

        // ---- in-warp column norms (butterfly over gid bits) ----
        float ss_e = d[0][0]*d[0][0] + d[0][2]*d[0][2] + d[1][0]*d[1][0] + d[1][2]*d[1][2];
        float ss_o = d[0][1]*d[0][1] + d[0][3]*d[0][3] + d[1][1]*d[1][1] + d[1][3]*d[1][3];
        #pragma unroll
        for (int off = 4; off <= 16; off <<= 1) {
            ss_e += __shfl_xor_sync(0xffffffffu, ss_e, off);
            ss_o += __shfl_xor_sync(0xffffffffu, ss_o, off);
        }
        float rn_e = rsqrtf(ss_e), rn_o = rsqrtf(ss_o);

        // ---- write Kn (tf32) to own column slice ----
        {
            int jj = jw + 2 * tig;
            ktu[(gid)      * STK + jj]     = f2tf(d[0][0] * rn_e);
            ktu[(gid)      * STK + jj + 1] = f2tf(d[0][1] * rn_o);
            ktu[(gid + 8)  * STK + jj]     = f2tf(d[0][2] * rn_e);
            ktu[(gid + 8)  * STK + jj + 1] = f2tf(d[0][3] * rn_o);
            ktu[(gid + 16) * STK + jj]     = f2tf(d[1][0] * rn_e);
            ktu[(gid + 16) * STK + jj + 1] = f2tf(d[1][1] * rn_o);
            ktu[(gid + 24) * STK + jj]     = f2tf(d[1][2] * rn_e);
            ktu[(gid + 24) * STK + jj + 1] = f2tf(d[1][3] * rn_o);
        }
        __syncthreads();                         // Kn visible to all

        // ---- xsum partial (exact fp32, row c = tid) ----
        {
            float s = 0.f;
            #pragma unroll
            for (int q = 0; q < 16; q++) {
                float4 v = *(const float4*)&xs[tid * STX + 4 * q];
                s += v.x + v.y + v.z + v.w;
            }
            xsum_acc += s;
        }
        // ---- S partial (row m = tid, warp 0 only) ----
        if (tid < 32) {
            float s = 0.f;
            #pragma unroll
            for (int q = 0; q < 16; q++) {
                float4 v = *(const float4*)&kt[tid * STK + 4 * q];
                s += v.x + v.y + v.z + v.w;
            }
            S_acc += s;
        }

        // ---- mpT accumulate: e[c][m] += x-subtile @ Kn^T (k = 64) ----
        #pragma unroll
        for (int kk = 0; kk < 8; kk++) {
            int j0 = kk * 8;
            uint32_t bb0[4], bb1[4];
            #pragma unroll
            for (int mt = 0; mt < 4; mt++) {
                bb0[mt] = ktu[(mt * 8 + gid) * STK + j0 + tig];
                bb1[mt] = ktu[(mt * 8 + gid) * STK + j0 + 4 + tig];
            }
            #pragma unroll
            for (int ct = 0; ct < 2; ct++) {
                int c0 = (2 * w + ct) * 16;
                uint32_t a0 = f2tf(xs[(c0 + gid) * STX + j0 + tig]);
                uint32_t a1 = f2tf(xs[(c0 + 8 + gid) * STX + j0 + tig]);
                uint32_t a2 = f2tf(xs[(c0 + gid) * STX + j0 + 4 + tig]);
                uint32_t a3 = f2tf(xs[(c0 + 8 + gid) * STX + j0 + 4 + tig]);
                #pragma unroll
                for (int mt = 0; mt < 4; mt++)
                    mma_tf32(e[ct][mt][0], e[ct][mt][1], e[ct][mt][2], e[ct][mt][3],
                             a0, a1, a2, a3, bb0[mt], bb1[mt]);
            }
        }
        __syncthreads();                         // all xs/kt reads done
        if (ch < 3) {
            stage_issue(xs, xb, n0 + (ch + 1) * SUB, tid);
            cp_commit();
        }
    }

    // ---- final global reductions ----
    atomicAdd(&g_xsum[b * CC + tid], xsum_acc);
    if (tid < 32) atomicAdd(&g_S[b * CQ + tid], S_acc);
    float* mpb = &g_mpT[b * CC * CQ];
    #pragma unroll
    for (int ct = 0; ct < 2; ct++) {
        int c0 = (2 * w + ct) * 16;
        #pragma unroll
        for (int mt = 0; mt < 4; mt++) {
            int m0 = mt * 8 + 2 * tig;
            atomicAdd(&mpb[(c0 + gid) * CQ + m0],         e[ct][mt][0]);
            atomicAdd(&mpb[(c0 + gid) * CQ + m0 + 1],     e[ct][mt][1]);
            atomicAdd(&mpb[(c0 + 8 + gid) * CQ + m0],     e[ct][mt][2]);
            atomicAdd(&mpb[(c0 + 8 + gid) * CQ + m0 + 1], e[ct][mt][3]);
        }
    }
}

// ---------------- kernel 2: matrix = mp @ Wv^T + bv (x) S ; vsum; fragments -
__global__ void __launch_bounds__(256)
k_mat(const float* __restrict__ Wv, const float* __restrict__ bv) {
    __shared__ float mpT[CC * CQ];   // [c][m]
    __shared__ float xs_s[CC];
    __shared__ float S_s[CQ];
    const int b = blockIdx.x, tid = threadIdx.x;

    for (int idx = tid; idx < CC * CQ; idx += 256)
        mpT[idx] = g_mpT[b * CC * CQ + idx];
    xs_s[tid] = g_xsum[b * CC + tid];
    if (tid < 32) S_s[tid] = g_S[b * CQ + tid];
    __syncthreads();

    const int cp = tid;
    float bvv = __ldg(&bv[cp]);
    float accm[32];
    #pragma unroll
    for (int m = 0; m < 32; m++) accm[m] = bvv * S_s[m];
    float vs = (float)NN * bvv;

    const float* wrow = Wv + cp * CC;
    for (int c = 0; c < CC; ++c) {
        float wv = __ldg(&wrow[c]);
        vs += wv * xs_s[c];
        const float4* mr = (const float4*)&mpT[c * CQ];
        #pragma unroll
        for (int q = 0; q < 8; q++) {
            float4 v = mr[q];
            accm[q * 4 + 0] += v.x * wv; accm[q * 4 + 1] += v.y * wv;
            accm[q * 4 + 2] += v.z * wv; accm[q * 4 + 3] += v.w * wv;
        }
    }
    g_vsum[b * CC + cp] = vs;

    const int ct = cp >> 4, cl = cp & 15;
    const int gid = cl & 7, hi = cl >> 3;
    #pragma unroll
    for (int m = 0; m < 32; m++) {
        int kk = m >> 3, tig = m & 3, half = (m >> 2) & 1;
        int elem = hi + 2 * half;
        g_mfrag[((((b * 16 + ct) * 4 + kk) * 32) + gid * 4 + tig) * 4 + elem] = f2tf(accm[m]);
    }
}

// ---------------- kernel 3: Q pass + TC epilogue (warp-autonomous) ----------
__global__ void __launch_bounds__(256, 2)
k_pass2(const float* __restrict__ x, const float* __restrict__ bq,
        const float* __restrict__ gamma, float* __restrict__ out) {
    extern __shared__ float sh[];
    float* xs   = sh;                     // [256][STX] fp32 x tile (also residual)
    float* qt   = sh + CC * STX;          // [32][STX]  Qn (tf32 bits)
    float* vs_s = qt + CQ * STX;          // [256]
    float* Se   = vs_s + CC;              // [32]
    uint32_t* qtu = (uint32_t*)qt;

    const int b   = blockIdx.x >> 8;
    const int n0  = (blockIdx.x & 255) * T2;
    const int tid = threadIdx.x;
    const int w = tid >> 5, lane = tid & 31, gid = lane >> 2, tig = lane & 3;
    const int jw = w * 8;
    const float* xb = x + (size_t)b * CC * NN;

    stage_issue(xs, xb, n0, tid);
    cp_commit();

    const float bq0 = __ldg(&bq[gid]);
    const float bq1 = __ldg(&bq[gid + 8]);
    const float bq2 = __ldg(&bq[gid + 16]);
    const float bq3 = __ldg(&bq[gid + 24]);
    const float gm  = __ldg(&gamma[0]);

    vs_s[tid] = g_vsum[b * CC + tid];
    if (tid < 32) Se[tid] = g_S[b * CQ + tid] + EPSV;

    cp_wait0();
    __syncthreads();                      // the ONLY block barrier

    // ---- warp-local: Q proj for own 8 j (k = 256) ----
    float d[2][4];
    #pragma unroll
    for (int wo = 0; wo < 2; wo++)
        #pragma unroll
        for (int q = 0; q < 4; q++) d[wo][q] = 0.f;
    {
        const uint4* W0 = (const uint4*)g_WtF + lane;
        const uint4* W1 = (const uint4*)g_WtF + 1024 + lane;
        #pragma unroll 4
        for (int kk = 0; kk < 32; kk++) {
            int c0 = kk * 8;
            uint32_t b0 = f2tf(xs[(c0 + tig) * STX + jw + gid]);
            uint32_t b1 = f2tf(xs[(c0 + 4 + tig) * STX + jw + gid]);
            uint4 a0 = W0[kk * 32];
            mma_tf32(d[0][0], d[0][1], d[0][2], d[0][3], a0.x, a0.y, a0.z, a0.w, b0, b1);
            uint4 a1 = W1[kk * 32];
            mma_tf32(d[1][0], d[1][1], d[1][2], d[1][3], a1.x, a1.y, a1.z, a1.w, b0, b1);
        }
    }
    d[0][0] += bq0; d[0][1] += bq0; d[0][2] += bq1; d[0][3] += bq1;
    d[1][0] += bq2; d[1][1] += bq2; d[1][2] += bq3; d[1][3] += bq3;

    // ---- merged in-warp reductions: ||Q||^2 and Q.(S+eps) ----
    const float se0 = Se[gid], se1 = Se[gid + 8], se2 = Se[gid + 16], se3 = Se[gid + 24];
    float ss_e = d[0][0]*d[0][0] + d[0][2]*d[0][2] + d[1][0]*d[1][0] + d[1][2]*d[1][2];
    float ss_o = d[0][1]*d[0][1] + d[0][3]*d[0][3] + d[1][1]*d[1][1] + d[1][3]*d[1][3];
    float te   = d[0][0]*se0 + d[0][2]*se1 + d[1][0]*se2 + d[1][2]*se3;
    float to   = d[0][1]*se0 + d[0][3]*se1 + d[1][1]*se2 + d[1][3]*se3;
    #pragma unroll
    for (int off = 4; off <= 16; off <<= 1) {
        ss_e += __shfl_xor_sync(0xffffffffu, ss_e, off);
        ss_o += __shfl_xor_sync(0xffffffffu, ss_o, off);
        te   += __shfl_xor_sync(0xffffffffu, te, off);
        to   += __shfl_xor_sync(0xffffffffu, to, off);
    }
    const float rn_e = rsqrtf(ss_e), rn_o = rsqrtf(ss_o);
    const float gt_e = gm / ((float)NN + rn_e * te);
    const float gt_o = gm / ((float)NN + rn_o * to);

    // ---- write Qn (tf32) to own column slice ----
    const int jj = jw + 2 * tig;
    qtu[(gid)      * STX + jj]     = f2tf(d[0][0] * rn_e);
    qtu[(gid)      * STX + jj + 1] = f2tf(d[0][1] * rn_o);
    qtu[(gid + 8)  * STX + jj]     = f2tf(d[0][2] * rn_e);
    qtu[(gid + 8)  * STX + jj + 1] = f2tf(d[0][3] * rn_o);
    qtu[(gid + 16) * STX + jj]     = f2tf(d[1][0] * rn_e);
    qtu[(gid + 16) * STX + jj + 1] = f2tf(d[1][1] * rn_o);
    qtu[(gid + 24) * STX + jj]     = f2tf(d[1][2] * rn_e);
    qtu[(gid + 24) * STX + jj + 1] = f2tf(d[1][3] * rn_o);
    __syncwarp();

    // ---- B fragments of Qn for own slice (k = 32 total) ----
    uint32_t B0[4], B1[4];
    #pragma unroll
    for (int kk = 0; kk < 4; kk++) {
        B0[kk] = qtu[(kk * 8 + tig) * STX + jw + gid];
        B1[kk] = qtu[(kk * 8 + 4 + tig) * STX + jw + gid];
    }

    // ---- D[256c x 8j] = matT @ Qn ; fused epilogue + store ----
    float* ob = out + (size_t)b * CC * NN + n0;
    const uint4* mf = (const uint4*)g_mfrag + (size_t)b * 16 * 4 * 32 + lane;
    #pragma unroll 4
    for (int ct = 0; ct < 16; ct++) {
        const uint4* base = mf + ct * 4 * 32;
        uint4 A0 = base[0], A1 = base[32], A2 = base[64], A3 = base[96];
        float e0 = 0.f, e1 = 0.f, e2 = 0.f, e3 = 0.f;
        mma_tf32(e0, e1, e2, e3, A0.x, A0.y, A0.z, A0.w, B0[0], B1[0]);
        mma_tf32(e0, e1, e2, e3, A1.x, A1.y, A1.z, A1.w, B0[1], B1[1]);
        mma_tf32(e0, e1, e2, e3, A2.x, A2.y, A2.z, A2.w, B0[2], B1[2]);
        mma_tf32(e0, e1, e2, e3, A3.x, A3.y, A3.z, A3.w, B0[3], B1[3]);

        const int c1 = ct * 16 + gid;
        const int c2 = c1 + 8;
        float2 x1 = *(const float2*)&xs[c1 * STX + jj];
        float2 x2 = *(const float2*)&xs[c2 * STX + jj];
        const float v1 = vs_s[c1], v2 = vs_s[c2];
        float2 o1, o2;
        o1.x = x1.x + gt_e * (v1 + e0);
        o1.y = x1.y + gt_o * (v1 + e1);
        o2.x = x2.x + gt_e * (v2 + e2);
        o2.y = x2.y + gt_o * (v2 + e3);
        *(float2*)(ob + (size_t)c1 * NN + jj) = o1;
        *(float2*)(ob + (size_t)c2 * NN + jj) = o2;
    }
}

// ---------------- launch --------------------------------------------------
extern "C" void kernel_launch(void* const* d_in, const int* in_sizes, int n_in,
                              void* d_out, int out_size) {
    const float* x     = (const float*)d_in[0];
    const float* Wq    = (const float*)d_in[1];
    const float* bq    = (const float*)d_in[2];
    const float* Wk    = (const float*)d_in[3];
    const float* bk    = (const float*)d_in[4];
    const float* Wv    = (const float*)d_in[5];
    const float* bv    = (const float*)d_in[6];
    const float* gamma = (const float*)d_in[7];
    float* out = (float*)d_out;

    const int sh1 = (CC * STX + CQ * STK) * (int)sizeof(float);            // 83,456 B
    const int sh2 = (CC * STX + CQ * STX + CC + CQ) * (int)sizeof(float);  // 84,096 B
    cudaFuncSetAttribute(k_pass1, cudaFuncAttributeMaxDynamicSharedMemorySize, sh1);
    cudaFuncSetAttribute(k_pass2, cudaFuncAttributeMaxDynamicSharedMemorySize, sh2);

    k_prep<<<256, 256>>>(Wq, Wk);
    k_pass1<<<BB * (NN / T1), 256, sh1>>>(x, bk);          // 512 blocks
    k_mat<<<BB, 256>>>(Wv, bv);
    k_pass2<<<BB * (NN / T2), 256, sh2>>>(x, bq, gamma, out);  // 2048 blocks
}